// round 13
// baseline (speedup 1.0000x reference)
#include <cuda_runtime.h>
#include <cuda_fp16.h>
#include <math.h>
#include <stdint.h>

#define BDIM 16
#define SDIM 4096
#define EDIM 512
#define HDIM 8
#define DH   64
#define TOK  (BDIM * SDIM)   // 65536 tokens
#define KDIM 512

// ---------------------------------------------------------------------------
// Scratch (allocation-free rule: device globals)
// ---------------------------------------------------------------------------
__device__ float   g_qkv[(size_t)TOK * 3 * EDIM];
__device__ __half  g_xh [(size_t)TOK * EDIM];
__device__ __half  g_oh [(size_t)TOK * EDIM];
__device__ __half  g_winh [(size_t)3 * EDIM * EDIM];
__device__ __half  g_wouth[(size_t)EDIM * EDIM];

// ---------------------------------------------------------------------------
// PTX helpers (base PTX only)
// ---------------------------------------------------------------------------
__device__ __forceinline__ uint32_t smem_u32(const void* p) {
    uint32_t a;
    asm("{ .reg .u64 t; cvta.to.shared.u64 t, %1; cvt.u32.u64 %0, t; }" : "=r"(a) : "l"(p));
    return a;
}
__device__ __forceinline__ void cpa16(uint32_t dst, const void* src) {
    asm volatile("cp.async.cg.shared.global [%0], [%1], 16;" :: "r"(dst), "l"(src));
}
#define CP_COMMIT() asm volatile("cp.async.commit_group;" ::: "memory")
#define CP_WAIT(n)  asm volatile("cp.async.wait_group %0;" :: "n"(n) : "memory")

__device__ __forceinline__ void ldsm4(uint32_t& r0, uint32_t& r1, uint32_t& r2, uint32_t& r3,
                                      uint32_t addr) {
    asm volatile("ldmatrix.sync.aligned.m8n8.x4.shared.b16 {%0,%1,%2,%3}, [%4];"
                 : "=r"(r0), "=r"(r1), "=r"(r2), "=r"(r3) : "r"(addr));
}
__device__ __forceinline__ void mma16816(float& d0, float& d1, float& d2, float& d3,
                                         uint32_t a0, uint32_t a1, uint32_t a2, uint32_t a3,
                                         uint32_t b0, uint32_t b1) {
    asm volatile(
        "mma.sync.aligned.m16n8k16.row.col.f32.f16.f16.f32 "
        "{%0,%1,%2,%3}, {%4,%5,%6,%7}, {%8,%9}, {%0,%1,%2,%3};"
        : "+f"(d0), "+f"(d1), "+f"(d2), "+f"(d3)
        : "r"(a0), "r"(a1), "r"(a2), "r"(a3), "r"(b0), "r"(b1));
}

// Swizzled offset in a 64-col fp16 tile (row = 128 B = 8 x 16B chunks)
__device__ __forceinline__ uint32_t swz128(int row, int ch) {
    return (uint32_t)(row * 128 + ((ch ^ (row & 7)) << 4));
}

// ---------------------------------------------------------------------------
// fp32 -> fp16 convert (vectorized)
// ---------------------------------------------------------------------------
__global__ void __launch_bounds__(256) conv_f16(
    const float4* __restrict__ x, uint2* __restrict__ h, int n4)
{
    int i = blockIdx.x * 256 + threadIdx.x;
    if (i >= n4) return;
    float4 v = x[i];
    __half2 a = __floats2half2_rn(v.x, v.y);
    __half2 b = __floats2half2_rn(v.z, v.w);
    uint2 o;
    o.x = *(uint32_t*)&a;
    o.y = *(uint32_t*)&b;
    h[i] = o;
}

// ---------------------------------------------------------------------------
// fp16 HMMA GEMM: C[M,N] = A[M,K]*B[N,K]^T + bias (fp32 out).
// CTA tile 128x256, warp tile 64x64 (8 warps = 2x4), BK=64, 8 iterations,
// 3 rotating 48KB stages (A 16KB | B 32KB), single sync, distance-2.
// Per k16: 8 ldsm -> 32-MMA uninterrupted stream (L1 1408 vs MMA 2048 cyc/SM-iter).
// ---------------------------------------------------------------------------
#define STAGES 3
#define ATILE 16384
#define BTILE 32768
#define STAGE_BYTES (ATILE + BTILE)
#define GEMM_SMEM (STAGES * STAGE_BYTES)   // 144KB
#define NCHUNK 8
#define BN_T 256

__global__ void __launch_bounds__(256, 1) gemm_hmma(
    const __half* __restrict__ A, const __half* __restrict__ B,
    const float* __restrict__ bias, float* __restrict__ C, int N)
{
    extern __shared__ char smem[];
    const uint32_t sb = smem_u32(smem);
    const int tid = threadIdx.x;
    const int wid = tid >> 5;
    const int lid = tid & 31;
    const int bm = blockIdx.y * 128;
    const int bn = blockIdx.x * BN_T;

    const int warp_m = (wid >> 2) * 64;   // 0 or 64
    const int warp_n = (wid & 3) * 64;    // 0,64,128,192

    const int lrow = tid >> 3;            // 0..31
    const int lch  = tid & 7;
    uint32_t dOff[8];
#pragma unroll
    for (int i = 0; i < 8; i++) dOff[i] = swz128(lrow + 32 * i, lch);

    const __half* pA = A + (size_t)(bm + lrow) * KDIM + lch * 8;
    const __half* pB = B + (size_t)(bn + lrow) * KDIM + lch * 8;

    float acc[4][8][4];
#pragma unroll
    for (int i = 0; i < 4; i++)
#pragma unroll
        for (int j = 0; j < 8; j++)
#pragma unroll
            for (int r = 0; r < 4; r++) acc[i][j][r] = 0.0f;

    uint32_t offA[4], offB[4];
#pragma unroll
    for (int fm = 0; fm < 4; fm++)
        offA[fm] = swz128(warp_m + fm * 16 + (lid & 15), lid >> 4);
#pragma unroll
    for (int fb = 0; fb < 4; fb++)
        offB[fb] = swz128(warp_n + fb * 16 + (lid & 15), lid >> 4);

    auto load_stage = [&](uint32_t sbase) {
#pragma unroll
        for (int i = 0; i < 4; i++)
            cpa16(sbase + dOff[i], pA + (size_t)(32 * i) * KDIM);
#pragma unroll
        for (int i = 0; i < 8; i++)
            cpa16(sbase + ATILE + dOff[i], pB + (size_t)(32 * i) * KDIM);
        pA += 64;
        pB += 64;
        CP_COMMIT();
    };

    uint32_t sCur = sb, sNxt = sb + STAGE_BYTES, sPrv = sb + 2 * STAGE_BYTES;

    load_stage(sCur);
    load_stage(sNxt);

    for (int it = 0; it < NCHUNK; it++) {
        if (it < NCHUNK - 1) { CP_WAIT(1); } else { CP_WAIT(0); }
        __syncthreads();

        if (it + 2 < NCHUNK) load_stage(sPrv);

#pragma unroll
        for (int kk = 0; kk < 4; kk++) {
            const uint32_t kx = (uint32_t)kk << 5;
            uint32_t a[4][4], b[4][4];
#pragma unroll
            for (int fm = 0; fm < 4; fm++)
                ldsm4(a[fm][0], a[fm][1], a[fm][2], a[fm][3],
                      sCur + (offA[fm] ^ kx));
#pragma unroll
            for (int fb = 0; fb < 4; fb++)
                ldsm4(b[fb][0], b[fb][1], b[fb][2], b[fb][3],
                      sCur + ATILE + (offB[fb] ^ kx));

#pragma unroll
            for (int fm = 0; fm < 4; fm++)
#pragma unroll
                for (int fn = 0; fn < 8; fn++) {
                    const int fb = fn >> 1, hh = fn & 1;
                    mma16816(acc[fm][fn][0], acc[fm][fn][1], acc[fm][fn][2], acc[fm][fn][3],
                             a[fm][0], a[fm][1], a[fm][2], a[fm][3],
                             b[fb][hh], b[fb][hh + 2]);
                }
        }

        const uint32_t t = sPrv;
        sPrv = sCur; sCur = sNxt; sNxt = t;
    }

    const int lr = lid >> 2;
    const int lc = (lid & 3) * 2;
#pragma unroll
    for (int fm = 0; fm < 4; fm++) {
#pragma unroll
        for (int fn = 0; fn < 8; fn++) {
            const int col = bn + warp_n + fn * 8 + lc;
            const float b0 = bias[col], b1 = bias[col + 1];
            const int row0 = bm + warp_m + fm * 16 + lr;
            float2 v0 = { acc[fm][fn][0] + b0, acc[fm][fn][1] + b1 };
            float2 v1 = { acc[fm][fn][2] + b0, acc[fm][fn][3] + b1 };
            *(float2*)(C + (size_t)row0 * N + col)       = v0;
            *(float2*)(C + (size_t)(row0 + 8) * N + col) = v1;
        }
    }
}

// ---------------------------------------------------------------------------
// Attention (R12, frozen): CTA = (s, head-group of 4), 128 threads, warp=head.
// ---------------------------------------------------------------------------
#define SPAD2 258
#define ATT_SMEM ((3 * BDIM * SPAD2 + 4 * BDIM * 17) * 4)

__global__ void __launch_bounds__(128, 4) attn_kernel(
    const float* __restrict__ qkv, __half* __restrict__ oh)
{
    const int s = blockIdx.x;
    const int g = blockIdx.y;
    extern __shared__ float sm[];
    float* q  = sm;
    float* k  = q + BDIM * SPAD2;
    float* v  = k + BDIM * SPAD2;
    float* sc = v + BDIM * SPAD2;

    const int tid = threadIdx.x;

#pragma unroll
    for (int i = 0; i < 24; i++) {
        const int idx = tid + 128 * i;
        const int r   = idx >> 10;
        const int rem = idx & 1023;
        const int b   = rem >> 6;
        const int col = (rem & 63) * 4;
        const float4 d = *(const float4*)(
            qkv + ((size_t)(b * SDIM + s)) * 1536 + r * 512 + g * 256 + col);
        float* dst = sm + r * (BDIM * SPAD2) + b * SPAD2 + col;
        dst[0] = d.x; dst[1] = d.y; dst[2] = d.z; dst[3] = d.w;
    }
    __syncthreads();

    const int w   = tid >> 5;
    const int lid = tid & 31;
    const int hd  = w * DH;
    float* scw = sc + w * (BDIM * 17);

    {
        const int bq  = lid & 15;
        const int bk0 = (lid >> 4) * 8;
        float acc[8];
#pragma unroll
        for (int j = 0; j < 8; j++) acc[j] = 0.0f;
        const float* qrow = q + bq * SPAD2 + hd;
#pragma unroll 8
        for (int d2 = 0; d2 < 32; d2++) {
            const float2 qv = *(const float2*)(qrow + 2 * d2);
#pragma unroll
            for (int j = 0; j < 8; j++) {
                const float2 kv = *(const float2*)(k + (bk0 + j) * SPAD2 + hd + 2 * d2);
                acc[j] += qv.x * kv.x + qv.y * kv.y;
            }
        }
#pragma unroll
        for (int j = 0; j < 8; j++)
            scw[bq * 17 + bk0 + j] = acc[j] * 0.125f;
    }
    __syncwarp();

    if (lid < 16) {
        float* row = scw + lid * 17;
        float m = -1e30f;
#pragma unroll
        for (int j = 0; j < 16; j++) m = fmaxf(m, row[j]);
        float sum = 0.0f;
        float e_[16];
#pragma unroll
        for (int j = 0; j < 16; j++) { e_[j] = expf(row[j] - m); sum += e_[j]; }
        const float inv = 1.0f / sum;
#pragma unroll
        for (int j = 0; j < 16; j++) row[j] = e_[j] * inv;
    }
    __syncwarp();

    {
        const int bq    = lid >> 1;
        const int dbase = (lid & 1) * 32;
        float o[32];
#pragma unroll
        for (int i = 0; i < 32; i++) o[i] = 0.0f;
#pragma unroll
        for (int bk = 0; bk < BDIM; bk++) {
            const float sv = scw[bq * 17 + bk];
            const float* vr = v + bk * SPAD2 + hd + dbase;
#pragma unroll
            for (int i2 = 0; i2 < 16; i2++) {
                const float2 vv = *(const float2*)(vr + 2 * i2);
                o[2 * i2]     += sv * vv.x;
                o[2 * i2 + 1] += sv * vv.y;
            }
        }
        uint32_t h2[16];
#pragma unroll
        for (int i2 = 0; i2 < 16; i2++) {
            __half2 hh = __floats2half2_rn(o[2 * i2], o[2 * i2 + 1]);
            h2[i2] = *(uint32_t*)&hh;
        }
        __half* dst = oh + ((size_t)(bq * SDIM + s)) * EDIM + (g * 4 + w) * DH + dbase;
#pragma unroll
        for (int c = 0; c < 4; c++) {
            uint4 pk = { h2[4 * c], h2[4 * c + 1], h2[4 * c + 2], h2[4 * c + 3] };
            *(uint4*)(dst + 8 * c) = pk;
        }
    }
}

// ---------------------------------------------------------------------------
extern "C" void kernel_launch(void* const* d_in, const int* in_sizes, int n_in,
                              void* d_out, int out_size)
{
    const float* x     = (const float*)d_in[0];
    const float* W_in  = (const float*)d_in[1];
    const float* b_in  = (const float*)d_in[2];
    const float* W_out = (const float*)d_in[3];
    const float* b_out = (const float*)d_in[4];
    float* out = (float*)d_out;

    float* qkv;
    __half *xh, *oh, *winh, *wouth;
    cudaGetSymbolAddress((void**)&qkv, g_qkv);
    cudaGetSymbolAddress((void**)&xh, g_xh);
    cudaGetSymbolAddress((void**)&oh, g_oh);
    cudaGetSymbolAddress((void**)&winh, g_winh);
    cudaGetSymbolAddress((void**)&wouth, g_wouth);

    cudaFuncSetAttribute(gemm_hmma, cudaFuncAttributeMaxDynamicSharedMemorySize, GEMM_SMEM);
    cudaFuncSetAttribute(attn_kernel, cudaFuncAttributeMaxDynamicSharedMemorySize, ATT_SMEM);

    // fp32 -> fp16 conversions
    {
        int n4 = TOK * EDIM / 4;
        conv_f16<<<(n4 + 255) / 256, 256>>>((const float4*)x, (uint2*)xh, n4);
        n4 = 3 * EDIM * EDIM / 4;
        conv_f16<<<(n4 + 255) / 256, 256>>>((const float4*)W_in, (uint2*)winh, n4);
        n4 = EDIM * EDIM / 4;
        conv_f16<<<(n4 + 255) / 256, 256>>>((const float4*)W_out, (uint2*)wouth, n4);
    }

    // 1) QKV projection -> fp32 qkv   (N = 1536 -> 6 N-tiles)
    dim3 g1(3 * EDIM / BN_T, TOK / 128);
    gemm_hmma<<<g1, 256, GEMM_SMEM>>>(xh, winh, b_in, qkv, 3 * EDIM);

    // 2) Attention
    dim3 g2(SDIM, HDIM / 4);
    attn_kernel<<<g2, 128, ATT_SMEM>>>(qkv, oh);

    // 3) Output projection   (N = 512 -> 2 N-tiles)
    dim3 g3(EDIM / BN_T, TOK / 128);
    gemm_hmma<<<g3, 256, GEMM_SMEM>>>(oh, wouth, b_out, out, EDIM);
}

// round 14
// speedup vs baseline: 1.6372x; 1.6372x over previous
#include <cuda_runtime.h>
#include <cuda_fp16.h>
#include <math.h>
#include <stdint.h>

#define BDIM 16
#define SDIM 4096
#define EDIM 512
#define HDIM 8
#define DH   64
#define TOK  (BDIM * SDIM)   // 65536 tokens
#define KDIM 512

// ---------------------------------------------------------------------------
// Scratch (allocation-free rule: device globals)
// ---------------------------------------------------------------------------
__device__ float   g_qkv[(size_t)TOK * 3 * EDIM];
__device__ __half  g_xh [(size_t)TOK * EDIM];
__device__ __half  g_oh [(size_t)TOK * EDIM];
__device__ __half  g_winh [(size_t)3 * EDIM * EDIM];
__device__ __half  g_wouth[(size_t)EDIM * EDIM];

// ---------------------------------------------------------------------------
// PTX helpers (base PTX only)
// ---------------------------------------------------------------------------
__device__ __forceinline__ uint32_t smem_u32(const void* p) {
    uint32_t a;
    asm("{ .reg .u64 t; cvta.to.shared.u64 t, %1; cvt.u32.u64 %0, t; }" : "=r"(a) : "l"(p));
    return a;
}
__device__ __forceinline__ void cpa16(uint32_t dst, const void* src) {
    asm volatile("cp.async.cg.shared.global [%0], [%1], 16;" :: "r"(dst), "l"(src));
}
#define CP_COMMIT() asm volatile("cp.async.commit_group;" ::: "memory")
#define CP_WAIT(n)  asm volatile("cp.async.wait_group %0;" :: "n"(n) : "memory")

__device__ __forceinline__ void ldsm4(uint32_t& r0, uint32_t& r1, uint32_t& r2, uint32_t& r3,
                                      uint32_t addr) {
    asm volatile("ldmatrix.sync.aligned.m8n8.x4.shared.b16 {%0,%1,%2,%3}, [%4];"
                 : "=r"(r0), "=r"(r1), "=r"(r2), "=r"(r3) : "r"(addr));
}
__device__ __forceinline__ void mma16816(float& d0, float& d1, float& d2, float& d3,
                                         uint32_t a0, uint32_t a1, uint32_t a2, uint32_t a3,
                                         uint32_t b0, uint32_t b1) {
    asm volatile(
        "mma.sync.aligned.m16n8k16.row.col.f32.f16.f16.f32 "
        "{%0,%1,%2,%3}, {%4,%5,%6,%7}, {%8,%9}, {%0,%1,%2,%3};"
        : "+f"(d0), "+f"(d1), "+f"(d2), "+f"(d3)
        : "r"(a0), "r"(a1), "r"(a2), "r"(a3), "r"(b0), "r"(b1));
}

// Swizzled offset in a 64-col fp16 tile (row = 128 B = 8 x 16B chunks)
__device__ __forceinline__ uint32_t swz128(int row, int ch) {
    return (uint32_t)(row * 128 + ((ch ^ (row & 7)) << 4));
}

// ---------------------------------------------------------------------------
// fp32 -> fp16 convert: single launch covering x, W_in, W_out
// ---------------------------------------------------------------------------
#define N4_X  (TOK * EDIM / 4)
#define N4_WI (3 * EDIM * EDIM / 4)
#define N4_WO (EDIM * EDIM / 4)
#define NB_X  ((N4_X  + 255) / 256)
#define NB_WI ((N4_WI + 255) / 256)
#define NB_WO ((N4_WO + 255) / 256)

__global__ void __launch_bounds__(256) conv_all(
    const float4* __restrict__ x,  uint2* __restrict__ xh,
    const float4* __restrict__ wi, uint2* __restrict__ wih,
    const float4* __restrict__ wo, uint2* __restrict__ woh)
{
    int blk = blockIdx.x;
    const float4* src;
    uint2* dst;
    int i, n4;
    if (blk < NB_X)                 { src = x;  dst = xh;  i = blk * 256 + threadIdx.x;               n4 = N4_X; }
    else if (blk < NB_X + NB_WI)    { src = wi; dst = wih; i = (blk - NB_X) * 256 + threadIdx.x;      n4 = N4_WI; }
    else                            { src = wo; dst = woh; i = (blk - NB_X - NB_WI) * 256 + threadIdx.x; n4 = N4_WO; }
    if (i >= n4) return;
    float4 v = src[i];
    __half2 a = __floats2half2_rn(v.x, v.y);
    __half2 b = __floats2half2_rn(v.z, v.w);
    uint2 o;
    o.x = *(uint32_t*)&a;
    o.y = *(uint32_t*)&b;
    dst[i] = o;
}

// ---------------------------------------------------------------------------
// fp16 HMMA GEMM: C[M,N] = A[M,K]*B[N,K]^T + bias (fp32 out).
// CTA tile 128x128 with FOUR warps (2x2), warp tile 64x64, BK=64, 8 iters,
// 3 rotating 32KB stages, single sync, distance-2 prefetch, 2 CTAs/SM.
// Per k16 per warp: 8 ldsm -> 32-MMA stream; 2 desynchronized CTAs per SM.
// ---------------------------------------------------------------------------
#define STAGES 3
#define TILE16K 16384
#define STAGE_BYTES (2 * TILE16K)
#define GEMM_SMEM (STAGES * STAGE_BYTES)   // 96KB
#define NCHUNK 8

__global__ void __launch_bounds__(128, 2) gemm_hmma(
    const __half* __restrict__ A, const __half* __restrict__ B,
    const float* __restrict__ bias, float* __restrict__ C, int N)
{
    extern __shared__ char smem[];
    const uint32_t sb = smem_u32(smem);
    const int tid = threadIdx.x;
    const int wid = tid >> 5;
    const int lid = tid & 31;
    const int bm = blockIdx.y * 128;
    const int bn = blockIdx.x * 128;

    const int warp_m = (wid >> 1) * 64;   // 0 or 64
    const int warp_n = (wid & 1) * 64;    // 0 or 64

    // ---- load addressing: 128 threads, 16 rows x 8 chunks per round
    const int lrow = tid >> 3;            // 0..15
    const int lch  = tid & 7;
    uint32_t dOff[8];
#pragma unroll
    for (int i = 0; i < 8; i++) dOff[i] = swz128(lrow + 16 * i, lch);

    const __half* pA = A + (size_t)(bm + lrow) * KDIM + lch * 8;
    const __half* pB = B + (size_t)(bn + lrow) * KDIM + lch * 8;

    float acc[4][8][4];
#pragma unroll
    for (int i = 0; i < 4; i++)
#pragma unroll
        for (int j = 0; j < 8; j++)
#pragma unroll
            for (int r = 0; r < 4; r++) acc[i][j][r] = 0.0f;

    uint32_t offA[4], offB[4];
#pragma unroll
    for (int fm = 0; fm < 4; fm++)
        offA[fm] = swz128(warp_m + fm * 16 + (lid & 15), lid >> 4);
#pragma unroll
    for (int fb = 0; fb < 4; fb++)
        offB[fb] = swz128(warp_n + fb * 16 + (lid & 15), lid >> 4);

    auto load_stage = [&](uint32_t sbase) {
#pragma unroll
        for (int i = 0; i < 8; i++)
            cpa16(sbase + dOff[i], pA + (size_t)(16 * i) * KDIM);
#pragma unroll
        for (int i = 0; i < 8; i++)
            cpa16(sbase + TILE16K + dOff[i], pB + (size_t)(16 * i) * KDIM);
        pA += 64;
        pB += 64;
        CP_COMMIT();
    };

    uint32_t sCur = sb, sNxt = sb + STAGE_BYTES, sPrv = sb + 2 * STAGE_BYTES;

    load_stage(sCur);
    load_stage(sNxt);

    for (int it = 0; it < NCHUNK; it++) {
        if (it < NCHUNK - 1) { CP_WAIT(1); } else { CP_WAIT(0); }
        __syncthreads();

        if (it + 2 < NCHUNK) load_stage(sPrv);

#pragma unroll
        for (int kk = 0; kk < 4; kk++) {
            const uint32_t kx = (uint32_t)kk << 5;
            uint32_t a[4][4], b[4][4];
#pragma unroll
            for (int fm = 0; fm < 4; fm++)
                ldsm4(a[fm][0], a[fm][1], a[fm][2], a[fm][3],
                      sCur + (offA[fm] ^ kx));
#pragma unroll
            for (int fb = 0; fb < 4; fb++)
                ldsm4(b[fb][0], b[fb][1], b[fb][2], b[fb][3],
                      sCur + TILE16K + (offB[fb] ^ kx));

#pragma unroll
            for (int fm = 0; fm < 4; fm++)
#pragma unroll
                for (int fn = 0; fn < 8; fn++) {
                    const int fb = fn >> 1, hh = fn & 1;
                    mma16816(acc[fm][fn][0], acc[fm][fn][1], acc[fm][fn][2], acc[fm][fn][3],
                             a[fm][0], a[fm][1], a[fm][2], a[fm][3],
                             b[fb][hh], b[fb][hh + 2]);
                }
        }

        const uint32_t t = sPrv;
        sPrv = sCur; sCur = sNxt; sNxt = t;
    }

    // ---- Epilogue: fp32 stores + bias
    const int lr = lid >> 2;
    const int lc = (lid & 3) * 2;
#pragma unroll
    for (int fm = 0; fm < 4; fm++) {
#pragma unroll
        for (int fn = 0; fn < 8; fn++) {
            const int col = bn + warp_n + fn * 8 + lc;
            const float b0 = bias[col], b1 = bias[col + 1];
            const int row0 = bm + warp_m + fm * 16 + lr;
            float2 v0 = { acc[fm][fn][0] + b0, acc[fm][fn][1] + b1 };
            float2 v1 = { acc[fm][fn][2] + b0, acc[fm][fn][3] + b1 };
            *(float2*)(C + (size_t)row0 * N + col)       = v0;
            *(float2*)(C + (size_t)(row0 + 8) * N + col) = v1;
        }
    }
}

// ---------------------------------------------------------------------------
// Attention (R12, frozen): CTA = (s, head-group of 4), 128 threads, warp=head.
// ---------------------------------------------------------------------------
#define SPAD2 258
#define ATT_SMEM ((3 * BDIM * SPAD2 + 4 * BDIM * 17) * 4)

__global__ void __launch_bounds__(128, 4) attn_kernel(
    const float* __restrict__ qkv, __half* __restrict__ oh)
{
    const int s = blockIdx.x;
    const int g = blockIdx.y;
    extern __shared__ float sm[];
    float* q  = sm;
    float* k  = q + BDIM * SPAD2;
    float* v  = k + BDIM * SPAD2;
    float* sc = v + BDIM * SPAD2;

    const int tid = threadIdx.x;

#pragma unroll
    for (int i = 0; i < 24; i++) {
        const int idx = tid + 128 * i;
        const int r   = idx >> 10;
        const int rem = idx & 1023;
        const int b   = rem >> 6;
        const int col = (rem & 63) * 4;
        const float4 d = *(const float4*)(
            qkv + ((size_t)(b * SDIM + s)) * 1536 + r * 512 + g * 256 + col);
        float* dst = sm + r * (BDIM * SPAD2) + b * SPAD2 + col;
        dst[0] = d.x; dst[1] = d.y; dst[2] = d.z; dst[3] = d.w;
    }
    __syncthreads();

    const int w   = tid >> 5;
    const int lid = tid & 31;
    const int hd  = w * DH;
    float* scw = sc + w * (BDIM * 17);

    {
        const int bq  = lid & 15;
        const int bk0 = (lid >> 4) * 8;
        float acc[8];
#pragma unroll
        for (int j = 0; j < 8; j++) acc[j] = 0.0f;
        const float* qrow = q + bq * SPAD2 + hd;
#pragma unroll 8
        for (int d2 = 0; d2 < 32; d2++) {
            const float2 qv = *(const float2*)(qrow + 2 * d2);
#pragma unroll
            for (int j = 0; j < 8; j++) {
                const float2 kv = *(const float2*)(k + (bk0 + j) * SPAD2 + hd + 2 * d2);
                acc[j] += qv.x * kv.x + qv.y * kv.y;
            }
        }
#pragma unroll
        for (int j = 0; j < 8; j++)
            scw[bq * 17 + bk0 + j] = acc[j] * 0.125f;
    }
    __syncwarp();

    if (lid < 16) {
        float* row = scw + lid * 17;
        float m = -1e30f;
#pragma unroll
        for (int j = 0; j < 16; j++) m = fmaxf(m, row[j]);
        float sum = 0.0f;
        float e_[16];
#pragma unroll
        for (int j = 0; j < 16; j++) { e_[j] = expf(row[j] - m); sum += e_[j]; }
        const float inv = 1.0f / sum;
#pragma unroll
        for (int j = 0; j < 16; j++) row[j] = e_[j] * inv;
    }
    __syncwarp();

    {
        const int bq    = lid >> 1;
        const int dbase = (lid & 1) * 32;
        float o[32];
#pragma unroll
        for (int i = 0; i < 32; i++) o[i] = 0.0f;
#pragma unroll
        for (int bk = 0; bk < BDIM; bk++) {
            const float sv = scw[bq * 17 + bk];
            const float* vr = v + bk * SPAD2 + hd + dbase;
#pragma unroll
            for (int i2 = 0; i2 < 16; i2++) {
                const float2 vv = *(const float2*)(vr + 2 * i2);
                o[2 * i2]     += sv * vv.x;
                o[2 * i2 + 1] += sv * vv.y;
            }
        }
        uint32_t h2[16];
#pragma unroll
        for (int i2 = 0; i2 < 16; i2++) {
            __half2 hh = __floats2half2_rn(o[2 * i2], o[2 * i2 + 1]);
            h2[i2] = *(uint32_t*)&hh;
        }
        __half* dst = oh + ((size_t)(bq * SDIM + s)) * EDIM + (g * 4 + w) * DH + dbase;
#pragma unroll
        for (int c = 0; c < 4; c++) {
            uint4 pk = { h2[4 * c], h2[4 * c + 1], h2[4 * c + 2], h2[4 * c + 3] };
            *(uint4*)(dst + 8 * c) = pk;
        }
    }
}

// ---------------------------------------------------------------------------
extern "C" void kernel_launch(void* const* d_in, const int* in_sizes, int n_in,
                              void* d_out, int out_size)
{
    const float* x     = (const float*)d_in[0];
    const float* W_in  = (const float*)d_in[1];
    const float* b_in  = (const float*)d_in[2];
    const float* W_out = (const float*)d_in[3];
    const float* b_out = (const float*)d_in[4];
    float* out = (float*)d_out;

    float* qkv;
    __half *xh, *oh, *winh, *wouth;
    cudaGetSymbolAddress((void**)&qkv, g_qkv);
    cudaGetSymbolAddress((void**)&xh, g_xh);
    cudaGetSymbolAddress((void**)&oh, g_oh);
    cudaGetSymbolAddress((void**)&winh, g_winh);
    cudaGetSymbolAddress((void**)&wouth, g_wouth);

    cudaFuncSetAttribute(gemm_hmma, cudaFuncAttributeMaxDynamicSharedMemorySize, GEMM_SMEM);
    cudaFuncSetAttribute(attn_kernel, cudaFuncAttributeMaxDynamicSharedMemorySize, ATT_SMEM);

    // fp32 -> fp16 conversions (single launch)
    conv_all<<<NB_X + NB_WI + NB_WO, 256>>>(
        (const float4*)x, (uint2*)xh,
        (const float4*)W_in, (uint2*)winh,
        (const float4*)W_out, (uint2*)wouth);

    // 1) QKV projection -> fp32 qkv
    dim3 g1(3 * EDIM / 128, TOK / 128);
    gemm_hmma<<<g1, 128, GEMM_SMEM>>>(xh, winh, b_in, qkv, 3 * EDIM);

    // 2) Attention
    dim3 g2(SDIM, HDIM / 4);
    attn_kernel<<<g2, 128, ATT_SMEM>>>(qkv, oh);

    // 3) Output projection
    dim3 g3(EDIM / 128, TOK / 128);
    gemm_hmma<<<g3, 128, GEMM_SMEM>>>(oh, wouth, b_out, out, EDIM);
}

// round 15
// speedup vs baseline: 1.7134x; 1.0466x over previous
#include <cuda_runtime.h>
#include <cuda_fp16.h>
#include <math.h>
#include <stdint.h>

#define BDIM 16
#define SDIM 4096
#define EDIM 512
#define HDIM 8
#define DH   64
#define TOK  (BDIM * SDIM)   // 65536 tokens
#define KDIM 512

// ---------------------------------------------------------------------------
// Scratch (allocation-free rule: device globals)
// ---------------------------------------------------------------------------
__device__ __half  g_qkv[(size_t)TOK * 3 * EDIM];   // fp16 qkv
__device__ __half  g_xh [(size_t)TOK * EDIM];
__device__ __half  g_oh [(size_t)TOK * EDIM];
__device__ __half  g_winh [(size_t)3 * EDIM * EDIM];
__device__ __half  g_wouth[(size_t)EDIM * EDIM];

// ---------------------------------------------------------------------------
// PTX helpers (base PTX only)
// ---------------------------------------------------------------------------
__device__ __forceinline__ uint32_t smem_u32(const void* p) {
    uint32_t a;
    asm("{ .reg .u64 t; cvta.to.shared.u64 t, %1; cvt.u32.u64 %0, t; }" : "=r"(a) : "l"(p));
    return a;
}
__device__ __forceinline__ void cpa16(uint32_t dst, const void* src) {
    asm volatile("cp.async.cg.shared.global [%0], [%1], 16;" :: "r"(dst), "l"(src));
}
#define CP_COMMIT() asm volatile("cp.async.commit_group;" ::: "memory")
#define CP_WAIT(n)  asm volatile("cp.async.wait_group %0;" :: "n"(n) : "memory")

__device__ __forceinline__ void ldsm4(uint32_t& r0, uint32_t& r1, uint32_t& r2, uint32_t& r3,
                                      uint32_t addr) {
    asm volatile("ldmatrix.sync.aligned.m8n8.x4.shared.b16 {%0,%1,%2,%3}, [%4];"
                 : "=r"(r0), "=r"(r1), "=r"(r2), "=r"(r3) : "r"(addr));
}
__device__ __forceinline__ void mma16816(float& d0, float& d1, float& d2, float& d3,
                                         uint32_t a0, uint32_t a1, uint32_t a2, uint32_t a3,
                                         uint32_t b0, uint32_t b1) {
    asm volatile(
        "mma.sync.aligned.m16n8k16.row.col.f32.f16.f16.f32 "
        "{%0,%1,%2,%3}, {%4,%5,%6,%7}, {%8,%9}, {%0,%1,%2,%3};"
        : "+f"(d0), "+f"(d1), "+f"(d2), "+f"(d3)
        : "r"(a0), "r"(a1), "r"(a2), "r"(a3), "r"(b0), "r"(b1));
}

// Swizzled offset in a 64-col fp16 tile (row = 128 B = 8 x 16B chunks)
__device__ __forceinline__ uint32_t swz128(int row, int ch) {
    return (uint32_t)(row * 128 + ((ch ^ (row & 7)) << 4));
}

// ---------------------------------------------------------------------------
// fp32 -> fp16 convert: single launch covering x, W_in, W_out
// ---------------------------------------------------------------------------
#define N4_X  (TOK * EDIM / 4)
#define N4_WI (3 * EDIM * EDIM / 4)
#define N4_WO (EDIM * EDIM / 4)
#define NB_X  ((N4_X  + 255) / 256)
#define NB_WI ((N4_WI + 255) / 256)
#define NB_WO ((N4_WO + 255) / 256)

__global__ void __launch_bounds__(256) conv_all(
    const float4* __restrict__ x,  uint2* __restrict__ xh,
    const float4* __restrict__ wi, uint2* __restrict__ wih,
    const float4* __restrict__ wo, uint2* __restrict__ woh)
{
    int blk = blockIdx.x;
    const float4* src;
    uint2* dst;
    int i, n4;
    if (blk < NB_X)                 { src = x;  dst = xh;  i = blk * 256 + threadIdx.x;               n4 = N4_X; }
    else if (blk < NB_X + NB_WI)    { src = wi; dst = wih; i = (blk - NB_X) * 256 + threadIdx.x;      n4 = N4_WI; }
    else                            { src = wo; dst = woh; i = (blk - NB_X - NB_WI) * 256 + threadIdx.x; n4 = N4_WO; }
    if (i >= n4) return;
    float4 v = src[i];
    __half2 a = __floats2half2_rn(v.x, v.y);
    __half2 b = __floats2half2_rn(v.z, v.w);
    uint2 o;
    o.x = *(uint32_t*)&a;
    o.y = *(uint32_t*)&b;
    dst[i] = o;
}

// ---------------------------------------------------------------------------
// fp16 HMMA GEMM (R14 config): CTA 128x128, 4 warps (2x2, 64x64 each), BK=64,
// 8 iters, 3 rotating 32KB stages, 2 CTAs/SM. HALF_OUT stages the fp16 tile
// through smem for fully-coalesced 16B stores.
// ---------------------------------------------------------------------------
#define STAGES 3
#define TILE16K 16384
#define STAGE_BYTES (2 * TILE16K)
#define GEMM_SMEM (STAGES * STAGE_BYTES)   // 96KB
#define NCHUNK 8
#define SROW 136                            // half stride for epilogue staging

template<bool HALF_OUT>
__global__ void __launch_bounds__(128, 2) gemm_hmma(
    const __half* __restrict__ A, const __half* __restrict__ B,
    const float* __restrict__ bias, void* __restrict__ Cv, int N)
{
    extern __shared__ char smem[];
    const uint32_t sb = smem_u32(smem);
    const int tid = threadIdx.x;
    const int wid = tid >> 5;
    const int lid = tid & 31;
    const int bm = blockIdx.y * 128;
    const int bn = blockIdx.x * 128;

    const int warp_m = (wid >> 1) * 64;   // 0 or 64
    const int warp_n = (wid & 1) * 64;    // 0 or 64

    const int lrow = tid >> 3;            // 0..15
    const int lch  = tid & 7;
    uint32_t dOff[8];
#pragma unroll
    for (int i = 0; i < 8; i++) dOff[i] = swz128(lrow + 16 * i, lch);

    const __half* pA = A + (size_t)(bm + lrow) * KDIM + lch * 8;
    const __half* pB = B + (size_t)(bn + lrow) * KDIM + lch * 8;

    float acc[4][8][4];
#pragma unroll
    for (int i = 0; i < 4; i++)
#pragma unroll
        for (int j = 0; j < 8; j++)
#pragma unroll
            for (int r = 0; r < 4; r++) acc[i][j][r] = 0.0f;

    uint32_t offA[4], offB[4];
#pragma unroll
    for (int fm = 0; fm < 4; fm++)
        offA[fm] = swz128(warp_m + fm * 16 + (lid & 15), lid >> 4);
#pragma unroll
    for (int fb = 0; fb < 4; fb++)
        offB[fb] = swz128(warp_n + fb * 16 + (lid & 15), lid >> 4);

    auto load_stage = [&](uint32_t sbase) {
#pragma unroll
        for (int i = 0; i < 8; i++)
            cpa16(sbase + dOff[i], pA + (size_t)(16 * i) * KDIM);
#pragma unroll
        for (int i = 0; i < 8; i++)
            cpa16(sbase + TILE16K + dOff[i], pB + (size_t)(16 * i) * KDIM);
        pA += 64;
        pB += 64;
        CP_COMMIT();
    };

    uint32_t sCur = sb, sNxt = sb + STAGE_BYTES, sPrv = sb + 2 * STAGE_BYTES;

    load_stage(sCur);
    load_stage(sNxt);

    for (int it = 0; it < NCHUNK; it++) {
        if (it < NCHUNK - 1) { CP_WAIT(1); } else { CP_WAIT(0); }
        __syncthreads();

        if (it + 2 < NCHUNK) load_stage(sPrv);

#pragma unroll
        for (int kk = 0; kk < 4; kk++) {
            const uint32_t kx = (uint32_t)kk << 5;
            uint32_t a[4][4], b[4][4];
#pragma unroll
            for (int fm = 0; fm < 4; fm++)
                ldsm4(a[fm][0], a[fm][1], a[fm][2], a[fm][3],
                      sCur + (offA[fm] ^ kx));
#pragma unroll
            for (int fb = 0; fb < 4; fb++)
                ldsm4(b[fb][0], b[fb][1], b[fb][2], b[fb][3],
                      sCur + TILE16K + (offB[fb] ^ kx));

#pragma unroll
            for (int fm = 0; fm < 4; fm++)
#pragma unroll
                for (int fn = 0; fn < 8; fn++) {
                    const int fb = fn >> 1, hh = fn & 1;
                    mma16816(acc[fm][fn][0], acc[fm][fn][1], acc[fm][fn][2], acc[fm][fn][3],
                             a[fm][0], a[fm][1], a[fm][2], a[fm][3],
                             b[fb][hh], b[fb][hh + 2]);
                }
        }

        const uint32_t t = sPrv;
        sPrv = sCur; sCur = sNxt; sNxt = t;
    }

    const int lr = lid >> 2;
    const int lc = (lid & 3) * 2;

    if (HALF_OUT) {
        // Stage fp16 tile in smem (row skew kills bank conflicts), then
        // fully-coalesced 16B stores.
        __syncthreads();
        __half* sh = (__half*)smem;
#pragma unroll
        for (int fm = 0; fm < 4; fm++) {
#pragma unroll
            for (int fn = 0; fn < 8; fn++) {
                const int col = warp_n + fn * 8 + lc;
                const float b0 = bias[bn + col], b1 = bias[bn + col + 1];
                const int row0 = warp_m + fm * 16 + lr;
                __half2 h0 = __floats2half2_rn(acc[fm][fn][0] + b0, acc[fm][fn][1] + b1);
                __half2 h1 = __floats2half2_rn(acc[fm][fn][2] + b0, acc[fm][fn][3] + b1);
                *(__half2*)(sh + row0 * SROW + col)       = h0;
                *(__half2*)(sh + (row0 + 8) * SROW + col) = h1;
            }
        }
        __syncthreads();
        __half* C = (__half*)Cv;
#pragma unroll
        for (int i = 0; i < 16; i++) {
            const int idx = tid + 128 * i;     // 0..2047
            const int row = idx >> 4;
            const int c8  = (idx & 15) * 8;
            const uint4 vv = *(const uint4*)(sh + row * SROW + c8);
            *(uint4*)(C + (size_t)(bm + row) * N + bn + c8) = vv;
        }
    } else {
        float* C = (float*)Cv;
#pragma unroll
        for (int fm = 0; fm < 4; fm++) {
#pragma unroll
            for (int fn = 0; fn < 8; fn++) {
                const int col = bn + warp_n + fn * 8 + lc;
                const float b0 = bias[col], b1 = bias[col + 1];
                const int row0 = bm + warp_m + fm * 16 + lr;
                float2 v0 = { acc[fm][fn][0] + b0, acc[fm][fn][1] + b1 };
                float2 v1 = { acc[fm][fn][2] + b0, acc[fm][fn][3] + b1 };
                *(float2*)(C + (size_t)row0 * N + col)       = v0;
                *(float2*)(C + (size_t)(row0 + 8) * N + col) = v1;
            }
        }
    }
}

// ---------------------------------------------------------------------------
// Attention: CTA = (s, head-group of 4), 128 threads, warp = head.
// fp16 qkv in -> fp32 smem compute -> fp16 o out. One __syncthreads.
// ---------------------------------------------------------------------------
#define SPAD2 258
#define ATT_SMEM ((3 * BDIM * SPAD2 + 4 * BDIM * 17) * 4)

__global__ void __launch_bounds__(128, 4) attn_kernel(
    const __half* __restrict__ qkv, __half* __restrict__ oh)
{
    const int s = blockIdx.x;
    const int g = blockIdx.y;
    extern __shared__ float sm[];
    float* q  = sm;
    float* k  = q + BDIM * SPAD2;
    float* v  = k + BDIM * SPAD2;
    float* sc = v + BDIM * SPAD2;

    const int tid = threadIdx.x;

    // ---- coalesced load: 3 regions x 16 rows x 256 halves (32 uint4/row)
#pragma unroll
    for (int i = 0; i < 12; i++) {
        const int idx = tid + 128 * i;           // 0..1535
        const int r   = idx >> 9;                // region 0=q 1=k 2=v
        const int rem = idx & 511;
        const int b   = rem >> 5;
        const int col = (rem & 31) * 8;
        const uint4 d = *(const uint4*)(
            qkv + ((size_t)(b * SDIM + s)) * 1536 + r * 512 + g * 256 + col);
        float* dst = sm + r * (BDIM * SPAD2) + b * SPAD2 + col;
        const __half2* hp = (const __half2*)&d;
#pragma unroll
        for (int j = 0; j < 4; j++) {
            const float2 f = __half22float2(hp[j]);
            dst[2 * j]     = f.x;
            dst[2 * j + 1] = f.y;
        }
    }
    __syncthreads();

    const int w   = tid >> 5;
    const int lid = tid & 31;
    const int hd  = w * DH;
    float* scw = sc + w * (BDIM * 17);

    {
        const int bq  = lid & 15;
        const int bk0 = (lid >> 4) * 8;
        float acc[8];
#pragma unroll
        for (int j = 0; j < 8; j++) acc[j] = 0.0f;
        const float* qrow = q + bq * SPAD2 + hd;
#pragma unroll 8
        for (int d2 = 0; d2 < 32; d2++) {
            const float2 qv = *(const float2*)(qrow + 2 * d2);
#pragma unroll
            for (int j = 0; j < 8; j++) {
                const float2 kv = *(const float2*)(k + (bk0 + j) * SPAD2 + hd + 2 * d2);
                acc[j] += qv.x * kv.x + qv.y * kv.y;
            }
        }
#pragma unroll
        for (int j = 0; j < 8; j++)
            scw[bq * 17 + bk0 + j] = acc[j] * 0.125f;
    }
    __syncwarp();

    if (lid < 16) {
        float* row = scw + lid * 17;
        float m = -1e30f;
#pragma unroll
        for (int j = 0; j < 16; j++) m = fmaxf(m, row[j]);
        float sum = 0.0f;
        float e_[16];
#pragma unroll
        for (int j = 0; j < 16; j++) { e_[j] = expf(row[j] - m); sum += e_[j]; }
        const float inv = 1.0f / sum;
#pragma unroll
        for (int j = 0; j < 16; j++) row[j] = e_[j] * inv;
    }
    __syncwarp();

    {
        const int bq    = lid >> 1;
        const int dbase = (lid & 1) * 32;
        float o[32];
#pragma unroll
        for (int i = 0; i < 32; i++) o[i] = 0.0f;
#pragma unroll
        for (int bk = 0; bk < BDIM; bk++) {
            const float sv = scw[bq * 17 + bk];
            const float* vr = v + bk * SPAD2 + hd + dbase;
#pragma unroll
            for (int i2 = 0; i2 < 16; i2++) {
                const float2 vv = *(const float2*)(vr + 2 * i2);
                o[2 * i2]     += sv * vv.x;
                o[2 * i2 + 1] += sv * vv.y;
            }
        }
        uint32_t h2[16];
#pragma unroll
        for (int i2 = 0; i2 < 16; i2++) {
            __half2 hh = __floats2half2_rn(o[2 * i2], o[2 * i2 + 1]);
            h2[i2] = *(uint32_t*)&hh;
        }
        __half* dst = oh + ((size_t)(bq * SDIM + s)) * EDIM + (g * 4 + w) * DH + dbase;
#pragma unroll
        for (int c = 0; c < 4; c++) {
            uint4 pk = { h2[4 * c], h2[4 * c + 1], h2[4 * c + 2], h2[4 * c + 3] };
            *(uint4*)(dst + 8 * c) = pk;
        }
    }
}

// ---------------------------------------------------------------------------
extern "C" void kernel_launch(void* const* d_in, const int* in_sizes, int n_in,
                              void* d_out, int out_size)
{
    const float* x     = (const float*)d_in[0];
    const float* W_in  = (const float*)d_in[1];
    const float* b_in  = (const float*)d_in[2];
    const float* W_out = (const float*)d_in[3];
    const float* b_out = (const float*)d_in[4];
    float* out = (float*)d_out;

    __half *qkv, *xh, *oh, *winh, *wouth;
    cudaGetSymbolAddress((void**)&qkv, g_qkv);
    cudaGetSymbolAddress((void**)&xh, g_xh);
    cudaGetSymbolAddress((void**)&oh, g_oh);
    cudaGetSymbolAddress((void**)&winh, g_winh);
    cudaGetSymbolAddress((void**)&wouth, g_wouth);

    cudaFuncSetAttribute(gemm_hmma<true>,  cudaFuncAttributeMaxDynamicSharedMemorySize, GEMM_SMEM);
    cudaFuncSetAttribute(gemm_hmma<false>, cudaFuncAttributeMaxDynamicSharedMemorySize, GEMM_SMEM);
    cudaFuncSetAttribute(attn_kernel, cudaFuncAttributeMaxDynamicSharedMemorySize, ATT_SMEM);

    // fp32 -> fp16 conversions (single launch)
    conv_all<<<NB_X + NB_WI + NB_WO, 256>>>(
        (const float4*)x, (uint2*)xh,
        (const float4*)W_in, (uint2*)winh,
        (const float4*)W_out, (uint2*)wouth);

    // 1) QKV projection -> fp16 qkv (smem-staged coalesced stores)
    dim3 g1(3 * EDIM / 128, TOK / 128);
    gemm_hmma<true><<<g1, 128, GEMM_SMEM>>>(xh, winh, b_in, qkv, 3 * EDIM);

    // 2) Attention
    dim3 g2(SDIM, HDIM / 4);
    attn_kernel<<<g2, 128, ATT_SMEM>>>(qkv, oh);

    // 3) Output projection -> fp32 out
    dim3 g3(EDIM / 128, TOK / 128);
    gemm_hmma<false><<<g3, 128, GEMM_SMEM>>>(oh, wouth, b_out, out, EDIM);
}

// round 16
// speedup vs baseline: 2.1180x; 1.2361x over previous
#include <cuda_runtime.h>
#include <cuda_fp16.h>
#include <math.h>
#include <stdint.h>

#define BDIM 16
#define SDIM 4096
#define EDIM 512
#define HDIM 8
#define DH   64
#define TOK  (BDIM * SDIM)   // 65536 tokens
#define KDIM 512

// ---------------------------------------------------------------------------
// Scratch (allocation-free rule: device globals)
// ---------------------------------------------------------------------------
__device__ __half  g_qkv[(size_t)TOK * 3 * EDIM];   // fp16 qkv
__device__ __half  g_xh [(size_t)TOK * EDIM];
__device__ __half  g_oh [(size_t)TOK * EDIM];
__device__ __half  g_winh [(size_t)3 * EDIM * EDIM];
__device__ __half  g_wouth[(size_t)EDIM * EDIM];

// ---------------------------------------------------------------------------
// PTX helpers (base PTX only)
// ---------------------------------------------------------------------------
__device__ __forceinline__ uint32_t smem_u32(const void* p) {
    uint32_t a;
    asm("{ .reg .u64 t; cvta.to.shared.u64 t, %1; cvt.u32.u64 %0, t; }" : "=r"(a) : "l"(p));
    return a;
}
__device__ __forceinline__ void cpa16(uint32_t dst, const void* src) {
    asm volatile("cp.async.cg.shared.global [%0], [%1], 16;" :: "r"(dst), "l"(src));
}
#define CP_COMMIT() asm volatile("cp.async.commit_group;" ::: "memory")
#define CP_WAIT(n)  asm volatile("cp.async.wait_group %0;" :: "n"(n) : "memory")

__device__ __forceinline__ void ldsm4(uint32_t& r0, uint32_t& r1, uint32_t& r2, uint32_t& r3,
                                      uint32_t addr) {
    asm volatile("ldmatrix.sync.aligned.m8n8.x4.shared.b16 {%0,%1,%2,%3}, [%4];"
                 : "=r"(r0), "=r"(r1), "=r"(r2), "=r"(r3) : "r"(addr));
}
__device__ __forceinline__ void ldsm4t(uint32_t& r0, uint32_t& r1, uint32_t& r2, uint32_t& r3,
                                       uint32_t addr) {
    asm volatile("ldmatrix.sync.aligned.m8n8.x4.trans.shared.b16 {%0,%1,%2,%3}, [%4];"
                 : "=r"(r0), "=r"(r1), "=r"(r2), "=r"(r3) : "r"(addr));
}
__device__ __forceinline__ void mma16816(float& d0, float& d1, float& d2, float& d3,
                                         uint32_t a0, uint32_t a1, uint32_t a2, uint32_t a3,
                                         uint32_t b0, uint32_t b1) {
    asm volatile(
        "mma.sync.aligned.m16n8k16.row.col.f32.f16.f16.f32 "
        "{%0,%1,%2,%3}, {%4,%5,%6,%7}, {%8,%9}, {%0,%1,%2,%3};"
        : "+f"(d0), "+f"(d1), "+f"(d2), "+f"(d3)
        : "r"(a0), "r"(a1), "r"(a2), "r"(a3), "r"(b0), "r"(b1));
}

// Swizzled offset in a 64-col fp16 tile (row = 128 B = 8 x 16B chunks)
__device__ __forceinline__ uint32_t swz128(int row, int ch) {
    return (uint32_t)(row * 128 + ((ch ^ (row & 7)) << 4));
}

// ---------------------------------------------------------------------------
// fp32 -> fp16 convert: single launch covering x, W_in, W_out
// ---------------------------------------------------------------------------
#define N4_X  (TOK * EDIM / 4)
#define N4_WI (3 * EDIM * EDIM / 4)
#define N4_WO (EDIM * EDIM / 4)
#define NB_X  ((N4_X  + 255) / 256)
#define NB_WI ((N4_WI + 255) / 256)
#define NB_WO ((N4_WO + 255) / 256)

__global__ void __launch_bounds__(256) conv_all(
    const float4* __restrict__ x,  uint2* __restrict__ xh,
    const float4* __restrict__ wi, uint2* __restrict__ wih,
    const float4* __restrict__ wo, uint2* __restrict__ woh)
{
    int blk = blockIdx.x;
    const float4* src;
    uint2* dst;
    int i, n4;
    if (blk < NB_X)                 { src = x;  dst = xh;  i = blk * 256 + threadIdx.x;               n4 = N4_X; }
    else if (blk < NB_X + NB_WI)    { src = wi; dst = wih; i = (blk - NB_X) * 256 + threadIdx.x;      n4 = N4_WI; }
    else                            { src = wo; dst = woh; i = (blk - NB_X - NB_WI) * 256 + threadIdx.x; n4 = N4_WO; }
    if (i >= n4) return;
    float4 v = src[i];
    __half2 a = __floats2half2_rn(v.x, v.y);
    __half2 b = __floats2half2_rn(v.z, v.w);
    uint2 o;
    o.x = *(uint32_t*)&a;
    o.y = *(uint32_t*)&b;
    dst[i] = o;
}

// ---------------------------------------------------------------------------
// fp16 HMMA GEMM (R15, frozen): CTA 128x128, 4 warps (2x2, 64x64), BK=64,
// 3 stages, 2 CTAs/SM. HALF_OUT stages fp16 tile through smem.
// ---------------------------------------------------------------------------
#define STAGES 3
#define TILE16K 16384
#define STAGE_BYTES (2 * TILE16K)
#define GEMM_SMEM (STAGES * STAGE_BYTES)   // 96KB
#define NCHUNK 8
#define SROW 136

template<bool HALF_OUT>
__global__ void __launch_bounds__(128, 2) gemm_hmma(
    const __half* __restrict__ A, const __half* __restrict__ B,
    const float* __restrict__ bias, void* __restrict__ Cv, int N)
{
    extern __shared__ char smem[];
    const uint32_t sb = smem_u32(smem);
    const int tid = threadIdx.x;
    const int wid = tid >> 5;
    const int lid = tid & 31;
    const int bm = blockIdx.y * 128;
    const int bn = blockIdx.x * 128;

    const int warp_m = (wid >> 1) * 64;
    const int warp_n = (wid & 1) * 64;

    const int lrow = tid >> 3;
    const int lch  = tid & 7;
    uint32_t dOff[8];
#pragma unroll
    for (int i = 0; i < 8; i++) dOff[i] = swz128(lrow + 16 * i, lch);

    const __half* pA = A + (size_t)(bm + lrow) * KDIM + lch * 8;
    const __half* pB = B + (size_t)(bn + lrow) * KDIM + lch * 8;

    float acc[4][8][4];
#pragma unroll
    for (int i = 0; i < 4; i++)
#pragma unroll
        for (int j = 0; j < 8; j++)
#pragma unroll
            for (int r = 0; r < 4; r++) acc[i][j][r] = 0.0f;

    uint32_t offA[4], offB[4];
#pragma unroll
    for (int fm = 0; fm < 4; fm++)
        offA[fm] = swz128(warp_m + fm * 16 + (lid & 15), lid >> 4);
#pragma unroll
    for (int fb = 0; fb < 4; fb++)
        offB[fb] = swz128(warp_n + fb * 16 + (lid & 15), lid >> 4);

    auto load_stage = [&](uint32_t sbase) {
#pragma unroll
        for (int i = 0; i < 8; i++)
            cpa16(sbase + dOff[i], pA + (size_t)(16 * i) * KDIM);
#pragma unroll
        for (int i = 0; i < 8; i++)
            cpa16(sbase + TILE16K + dOff[i], pB + (size_t)(16 * i) * KDIM);
        pA += 64;
        pB += 64;
        CP_COMMIT();
    };

    uint32_t sCur = sb, sNxt = sb + STAGE_BYTES, sPrv = sb + 2 * STAGE_BYTES;

    load_stage(sCur);
    load_stage(sNxt);

    for (int it = 0; it < NCHUNK; it++) {
        if (it < NCHUNK - 1) { CP_WAIT(1); } else { CP_WAIT(0); }
        __syncthreads();

        if (it + 2 < NCHUNK) load_stage(sPrv);

#pragma unroll
        for (int kk = 0; kk < 4; kk++) {
            const uint32_t kx = (uint32_t)kk << 5;
            uint32_t a[4][4], b[4][4];
#pragma unroll
            for (int fm = 0; fm < 4; fm++)
                ldsm4(a[fm][0], a[fm][1], a[fm][2], a[fm][3],
                      sCur + (offA[fm] ^ kx));
#pragma unroll
            for (int fb = 0; fb < 4; fb++)
                ldsm4(b[fb][0], b[fb][1], b[fb][2], b[fb][3],
                      sCur + TILE16K + (offB[fb] ^ kx));

#pragma unroll
            for (int fm = 0; fm < 4; fm++)
#pragma unroll
                for (int fn = 0; fn < 8; fn++) {
                    const int fb = fn >> 1, hh = fn & 1;
                    mma16816(acc[fm][fn][0], acc[fm][fn][1], acc[fm][fn][2], acc[fm][fn][3],
                             a[fm][0], a[fm][1], a[fm][2], a[fm][3],
                             b[fb][hh], b[fb][hh + 2]);
                }
        }

        const uint32_t t = sPrv;
        sPrv = sCur; sCur = sNxt; sNxt = t;
    }

    const int lr = lid >> 2;
    const int lc = (lid & 3) * 2;

    if (HALF_OUT) {
        __syncthreads();
        __half* sh = (__half*)smem;
#pragma unroll
        for (int fm = 0; fm < 4; fm++) {
#pragma unroll
            for (int fn = 0; fn < 8; fn++) {
                const int col = warp_n + fn * 8 + lc;
                const float b0 = bias[bn + col], b1 = bias[bn + col + 1];
                const int row0 = warp_m + fm * 16 + lr;
                __half2 h0 = __floats2half2_rn(acc[fm][fn][0] + b0, acc[fm][fn][1] + b1);
                __half2 h1 = __floats2half2_rn(acc[fm][fn][2] + b0, acc[fm][fn][3] + b1);
                *(__half2*)(sh + row0 * SROW + col)       = h0;
                *(__half2*)(sh + (row0 + 8) * SROW + col) = h1;
            }
        }
        __syncthreads();
        __half* C = (__half*)Cv;
#pragma unroll
        for (int i = 0; i < 16; i++) {
            const int idx = tid + 128 * i;
            const int row = idx >> 4;
            const int c8  = (idx & 15) * 8;
            const uint4 vv = *(const uint4*)(sh + row * SROW + c8);
            *(uint4*)(C + (size_t)(bm + row) * N + bn + c8) = vv;
        }
    } else {
        float* C = (float*)Cv;
#pragma unroll
        for (int fm = 0; fm < 4; fm++) {
#pragma unroll
            for (int fn = 0; fn < 8; fn++) {
                const int col = bn + warp_n + fn * 8 + lc;
                const float b0 = bias[col], b1 = bias[col + 1];
                const int row0 = bm + warp_m + fm * 16 + lr;
                float2 v0 = { acc[fm][fn][0] + b0, acc[fm][fn][1] + b1 };
                float2 v1 = { acc[fm][fn][2] + b0, acc[fm][fn][3] + b1 };
                *(float2*)(C + (size_t)row0 * N + col)       = v0;
                *(float2*)(C + (size_t)(row0 + 8) * N + col) = v1;
            }
        }
    }
}

// ---------------------------------------------------------------------------
// MMA attention: CTA = (s, head-group of 4), 128 threads, warp = head.
// Scores via m16n8k16 (fp16 in, fp32 acc), register softmax (shfl in 4-lane
// groups), P->A-frag repack (layout identity, no shuffles), P*V via
// ldmatrix.trans. All-fp16 smem, row stride 72 halves (conflict-free ldsm).
// ---------------------------------------------------------------------------
#define RS    72                      // halves per row (64 data + 8 pad)
#define HSEG  (16 * RS)               // 1152 halves per (region, head)
#define ATT_SMEM ((12 * HSEG + 4 * HSEG) * 2)   // qkv 12 segs + o 4 segs = 36864 B

__global__ void __launch_bounds__(128, 6) attn_kernel(
    const __half* __restrict__ qkv, __half* __restrict__ oh)
{
    const int s = blockIdx.x;
    const int g = blockIdx.y;          // head group (4 heads)
    extern __shared__ char smraw[];
    __half* smh = (__half*)smraw;
    const uint32_t sb = smem_u32(smraw);
    const int tid = threadIdx.x;

    // ---- cp.async load: 3 regions x 4 heads x 16 rows x 8 chunks (16B)
#pragma unroll
    for (int i = 0; i < 12; i++) {
        const int idx = tid + 128 * i;        // 0..1535
        const int ch  = idx & 7;
        const int b   = (idx >> 3) & 15;
        const int hd  = (idx >> 7) & 3;
        const int rg  = idx >> 9;             // 0..2
        const __half* src = qkv + ((size_t)(b * SDIM + s)) * 1536
                          + rg * 512 + (g * 4 + hd) * 64 + ch * 8;
        const uint32_t dsth = (uint32_t)((rg * 4 + hd) * HSEG + b * RS + ch * 8);
        cpa16(sb + dsth * 2, src);
    }
    CP_COMMIT();
    CP_WAIT(0);
    __syncthreads();

    const int w   = tid >> 5;          // head within group
    const int lid = tid & 31;
    const int lr  = lid >> 2;          // 0..7
    const int lc  = lid & 3;           // 0..3

    const uint32_t qb = sb + (uint32_t)((0 + w) * HSEG) * 2;
    const uint32_t kb = sb + (uint32_t)((4 + w) * HSEG) * 2;
    const uint32_t vb = sb + (uint32_t)((8 + w) * HSEG) * 2;
    __half* os = smh + (12 + w) * HSEG;

    const uint32_t lOff = (uint32_t)((lid & 15) * (RS * 2) + (lid >> 4) * 16);

    // ---- scores: Q[16,64] x K[16,64]^T, fp32 acc
    float s0[4] = {0.f, 0.f, 0.f, 0.f};   // keys 0-7
    float s1[4] = {0.f, 0.f, 0.f, 0.f};   // keys 8-15
#pragma unroll
    for (int t = 0; t < 4; t++) {
        uint32_t a0, a1, a2, a3, k0, k1, k2, k3;
        ldsm4(a0, a1, a2, a3, qb + lOff + t * 32);
        ldsm4(k0, k1, k2, k3, kb + lOff + t * 32);
        mma16816(s0[0], s0[1], s0[2], s0[3], a0, a1, a2, a3, k0, k2);
        mma16816(s1[0], s1[1], s1[2], s1[3], a0, a1, a2, a3, k1, k3);
    }

    // ---- register softmax. Row lr: {s0[0],s0[1],s1[0],s1[1]};
    //      row lr+8: {s0[2],s0[3],s1[2],s1[3]}. Reduce across 4-lane group.
    const float scl = 0.125f;
#pragma unroll
    for (int j = 0; j < 4; j++) { s0[j] *= scl; s1[j] *= scl; }

    float m0 = fmaxf(fmaxf(s0[0], s0[1]), fmaxf(s1[0], s1[1]));
    m0 = fmaxf(m0, __shfl_xor_sync(0xffffffffu, m0, 1));
    m0 = fmaxf(m0, __shfl_xor_sync(0xffffffffu, m0, 2));
    float m1 = fmaxf(fmaxf(s0[2], s0[3]), fmaxf(s1[2], s1[3]));
    m1 = fmaxf(m1, __shfl_xor_sync(0xffffffffu, m1, 1));
    m1 = fmaxf(m1, __shfl_xor_sync(0xffffffffu, m1, 2));

    float p00 = expf(s0[0] - m0), p01 = expf(s0[1] - m0);
    float p10 = expf(s1[0] - m0), p11 = expf(s1[1] - m0);
    float q00 = expf(s0[2] - m1), q01 = expf(s0[3] - m1);
    float q10 = expf(s1[2] - m1), q11 = expf(s1[3] - m1);

    float sum0 = p00 + p01 + p10 + p11;
    sum0 += __shfl_xor_sync(0xffffffffu, sum0, 1);
    sum0 += __shfl_xor_sync(0xffffffffu, sum0, 2);
    float sum1 = q00 + q01 + q10 + q11;
    sum1 += __shfl_xor_sync(0xffffffffu, sum1, 1);
    sum1 += __shfl_xor_sync(0xffffffffu, sum1, 2);
    const float i0 = 1.0f / sum0;
    const float i1 = 1.0f / sum1;

    // ---- pack P into A fragments (C-frag -> A-frag layout identity)
    __half2 ha0 = __floats2half2_rn(p00 * i0, p01 * i0);   // (row lr,   k 2lc..)
    __half2 ha1 = __floats2half2_rn(q00 * i1, q01 * i1);   // (row lr+8, k 2lc..)
    __half2 ha2 = __floats2half2_rn(p10 * i0, p11 * i0);   // (row lr,   k 8+2lc..)
    __half2 ha3 = __floats2half2_rn(q10 * i1, q11 * i1);   // (row lr+8, k 8+2lc..)
    const uint32_t pa0 = *(uint32_t*)&ha0;
    const uint32_t pa1 = *(uint32_t*)&ha1;
    const uint32_t pa2 = *(uint32_t*)&ha2;
    const uint32_t pa3 = *(uint32_t*)&ha3;

    // ---- P[16,16] x V[16,64]: V^T via ldmatrix.trans; trans pairing (r0,r1)/(r2,r3)
    float o[8][4];
#pragma unroll
    for (int i = 0; i < 8; i++)
#pragma unroll
        for (int r = 0; r < 4; r++) o[i][r] = 0.0f;

#pragma unroll
    for (int t = 0; t < 4; t++) {
        uint32_t v0, v1, v2, v3;
        ldsm4t(v0, v1, v2, v3, vb + lOff + t * 32);
        mma16816(o[2 * t][0], o[2 * t][1], o[2 * t][2], o[2 * t][3],
                 pa0, pa1, pa2, pa3, v0, v1);
        mma16816(o[2 * t + 1][0], o[2 * t + 1][1], o[2 * t + 1][2], o[2 * t + 1][3],
                 pa0, pa1, pa2, pa3, v2, v3);
    }

    // ---- stage o (fp16) in smem, then CTA-wide coalesced 16B stores
#pragma unroll
    for (int nt = 0; nt < 8; nt++) {
        __half2 h0 = __floats2half2_rn(o[nt][0], o[nt][1]);
        __half2 h1 = __floats2half2_rn(o[nt][2], o[nt][3]);
        *(__half2*)(os + lr * RS + nt * 8 + 2 * lc)       = h0;
        *(__half2*)(os + (lr + 8) * RS + nt * 8 + 2 * lc) = h1;
    }
    __syncthreads();

#pragma unroll
    for (int i = 0; i < 4; i++) {
        const int idx = tid + 128 * i;        // 0..511
        const int row = idx >> 5;             // batch b
        const int c8  = (idx & 31) * 8;       // half col within 256
        const int hd2 = c8 >> 6;
        const int within = c8 & 63;
        const uint4 vv = *(const uint4*)(smh + (12 + hd2) * HSEG + row * RS + within);
        *(uint4*)(oh + ((size_t)(row * SDIM + s)) * EDIM + g * 256 + c8) = vv;
    }
}

// ---------------------------------------------------------------------------
extern "C" void kernel_launch(void* const* d_in, const int* in_sizes, int n_in,
                              void* d_out, int out_size)
{
    const float* x     = (const float*)d_in[0];
    const float* W_in  = (const float*)d_in[1];
    const float* b_in  = (const float*)d_in[2];
    const float* W_out = (const float*)d_in[3];
    const float* b_out = (const float*)d_in[4];
    float* out = (float*)d_out;

    __half *qkv, *xh, *oh, *winh, *wouth;
    cudaGetSymbolAddress((void**)&qkv, g_qkv);
    cudaGetSymbolAddress((void**)&xh, g_xh);
    cudaGetSymbolAddress((void**)&oh, g_oh);
    cudaGetSymbolAddress((void**)&winh, g_winh);
    cudaGetSymbolAddress((void**)&wouth, g_wouth);

    cudaFuncSetAttribute(gemm_hmma<true>,  cudaFuncAttributeMaxDynamicSharedMemorySize, GEMM_SMEM);
    cudaFuncSetAttribute(gemm_hmma<false>, cudaFuncAttributeMaxDynamicSharedMemorySize, GEMM_SMEM);
    cudaFuncSetAttribute(attn_kernel, cudaFuncAttributeMaxDynamicSharedMemorySize, ATT_SMEM);

    // fp32 -> fp16 conversions (single launch)
    conv_all<<<NB_X + NB_WI + NB_WO, 256>>>(
        (const float4*)x, (uint2*)xh,
        (const float4*)W_in, (uint2*)winh,
        (const float4*)W_out, (uint2*)wouth);

    // 1) QKV projection -> fp16 qkv
    dim3 g1(3 * EDIM / 128, TOK / 128);
    gemm_hmma<true><<<g1, 128, GEMM_SMEM>>>(xh, winh, b_in, qkv, 3 * EDIM);

    // 2) MMA attention
    dim3 g2(SDIM, HDIM / 4);
    attn_kernel<<<g2, 128, ATT_SMEM>>>(qkv, oh);

    // 3) Output projection -> fp32 out
    dim3 g3(EDIM / 128, TOK / 128);
    gemm_hmma<false><<<g3, 128, GEMM_SMEM>>>(oh, wouth, b_out, out, EDIM);
}

// round 17
// speedup vs baseline: 2.1188x; 1.0004x over previous
#include <cuda_runtime.h>
#include <cuda_fp16.h>
#include <math.h>
#include <stdint.h>

#define BDIM 16
#define SDIM 4096
#define EDIM 512
#define HDIM 8
#define DH   64
#define TOK  (BDIM * SDIM)   // 65536 tokens
#define KDIM 512

// ---------------------------------------------------------------------------
// Scratch (allocation-free rule: device globals)
// ---------------------------------------------------------------------------
__device__ __half  g_qkv[(size_t)TOK * 3 * EDIM];   // fp16 qkv
__device__ __half  g_xh [(size_t)TOK * EDIM];
__device__ __half  g_oh [(size_t)TOK * EDIM];
__device__ __half  g_winh [(size_t)3 * EDIM * EDIM];
__device__ __half  g_wouth[(size_t)EDIM * EDIM];

// ---------------------------------------------------------------------------
// PTX helpers (base PTX only)
// ---------------------------------------------------------------------------
__device__ __forceinline__ uint32_t smem_u32(const void* p) {
    uint32_t a;
    asm("{ .reg .u64 t; cvta.to.shared.u64 t, %1; cvt.u32.u64 %0, t; }" : "=r"(a) : "l"(p));
    return a;
}
__device__ __forceinline__ void cpa16(uint32_t dst, const void* src) {
    asm volatile("cp.async.cg.shared.global [%0], [%1], 16;" :: "r"(dst), "l"(src));
}
#define CP_COMMIT() asm volatile("cp.async.commit_group;" ::: "memory")
#define CP_WAIT(n)  asm volatile("cp.async.wait_group %0;" :: "n"(n) : "memory")

__device__ __forceinline__ void ldsm4(uint32_t& r0, uint32_t& r1, uint32_t& r2, uint32_t& r3,
                                      uint32_t addr) {
    asm volatile("ldmatrix.sync.aligned.m8n8.x4.shared.b16 {%0,%1,%2,%3}, [%4];"
                 : "=r"(r0), "=r"(r1), "=r"(r2), "=r"(r3) : "r"(addr));
}
__device__ __forceinline__ void ldsm4t(uint32_t& r0, uint32_t& r1, uint32_t& r2, uint32_t& r3,
                                       uint32_t addr) {
    asm volatile("ldmatrix.sync.aligned.m8n8.x4.trans.shared.b16 {%0,%1,%2,%3}, [%4];"
                 : "=r"(r0), "=r"(r1), "=r"(r2), "=r"(r3) : "r"(addr));
}
__device__ __forceinline__ void mma16816(float& d0, float& d1, float& d2, float& d3,
                                         uint32_t a0, uint32_t a1, uint32_t a2, uint32_t a3,
                                         uint32_t b0, uint32_t b1) {
    asm volatile(
        "mma.sync.aligned.m16n8k16.row.col.f32.f16.f16.f32 "
        "{%0,%1,%2,%3}, {%4,%5,%6,%7}, {%8,%9}, {%0,%1,%2,%3};"
        : "+f"(d0), "+f"(d1), "+f"(d2), "+f"(d3)
        : "r"(a0), "r"(a1), "r"(a2), "r"(a3), "r"(b0), "r"(b1));
}

// Swizzled offset in a 64-col fp16 tile (row = 128 B = 8 x 16B chunks)
__device__ __forceinline__ uint32_t swz128(int row, int ch) {
    return (uint32_t)(row * 128 + ((ch ^ (row & 7)) << 4));
}

// ---------------------------------------------------------------------------
// fp32 -> fp16 convert: single launch covering x, W_in, W_out
// ---------------------------------------------------------------------------
#define N4_X  (TOK * EDIM / 4)
#define N4_WI (3 * EDIM * EDIM / 4)
#define N4_WO (EDIM * EDIM / 4)
#define NB_X  ((N4_X  + 255) / 256)
#define NB_WI ((N4_WI + 255) / 256)
#define NB_WO ((N4_WO + 255) / 256)

__global__ void __launch_bounds__(256) conv_all(
    const float4* __restrict__ x,  uint2* __restrict__ xh,
    const float4* __restrict__ wi, uint2* __restrict__ wih,
    const float4* __restrict__ wo, uint2* __restrict__ woh)
{
    int blk = blockIdx.x;
    const float4* src;
    uint2* dst;
    int i, n4;
    if (blk < NB_X)                 { src = x;  dst = xh;  i = blk * 256 + threadIdx.x;               n4 = N4_X; }
    else if (blk < NB_X + NB_WI)    { src = wi; dst = wih; i = (blk - NB_X) * 256 + threadIdx.x;      n4 = N4_WI; }
    else                            { src = wo; dst = woh; i = (blk - NB_X - NB_WI) * 256 + threadIdx.x; n4 = N4_WO; }
    if (i >= n4) return;
    float4 v = src[i];
    __half2 a = __floats2half2_rn(v.x, v.y);
    __half2 b = __floats2half2_rn(v.z, v.w);
    uint2 o;
    o.x = *(uint32_t*)&a;
    o.y = *(uint32_t*)&b;
    dst[i] = o;
}

// ---------------------------------------------------------------------------
// fp16 HMMA GEMM: CTA 128x128, 4 warps (2x2, 64x64), BK=64, 3 stages,
// 2 CTAs/SM. Register double-buffered fragments: every ldsm burst is
// prefetched behind the previous 32-MMA stream (incl. cross-stage at kk=3).
// ---------------------------------------------------------------------------
#define STAGES 3
#define TILE16K 16384
#define STAGE_BYTES (2 * TILE16K)
#define GEMM_SMEM (STAGES * STAGE_BYTES)   // 96KB
#define NCHUNK 8
#define SROW 136

template<bool HALF_OUT>
__global__ void __launch_bounds__(128, 2) gemm_hmma(
    const __half* __restrict__ A, const __half* __restrict__ B,
    const float* __restrict__ bias, void* __restrict__ Cv, int N)
{
    extern __shared__ char smem[];
    const uint32_t sb = smem_u32(smem);
    const int tid = threadIdx.x;
    const int wid = tid >> 5;
    const int lid = tid & 31;
    const int bm = blockIdx.y * 128;
    const int bn = blockIdx.x * 128;

    const int warp_m = (wid >> 1) * 64;
    const int warp_n = (wid & 1) * 64;

    const int lrow = tid >> 3;
    const int lch  = tid & 7;
    uint32_t dOff[8];
#pragma unroll
    for (int i = 0; i < 8; i++) dOff[i] = swz128(lrow + 16 * i, lch);

    const __half* pA = A + (size_t)(bm + lrow) * KDIM + lch * 8;
    const __half* pB = B + (size_t)(bn + lrow) * KDIM + lch * 8;

    float acc[4][8][4];
#pragma unroll
    for (int i = 0; i < 4; i++)
#pragma unroll
        for (int j = 0; j < 8; j++)
#pragma unroll
            for (int r = 0; r < 4; r++) acc[i][j][r] = 0.0f;

    uint32_t offA[4], offB[4];
#pragma unroll
    for (int fm = 0; fm < 4; fm++)
        offA[fm] = swz128(warp_m + fm * 16 + (lid & 15), lid >> 4);
#pragma unroll
    for (int fb = 0; fb < 4; fb++)
        offB[fb] = swz128(warp_n + fb * 16 + (lid & 15), lid >> 4);

    auto load_stage = [&](uint32_t sbase) {
#pragma unroll
        for (int i = 0; i < 8; i++)
            cpa16(sbase + dOff[i], pA + (size_t)(16 * i) * KDIM);
#pragma unroll
        for (int i = 0; i < 8; i++)
            cpa16(sbase + TILE16K + dOff[i], pB + (size_t)(16 * i) * KDIM);
        pA += 64;
        pB += 64;
        CP_COMMIT();
    };

    uint32_t sCur = sb, sNxt = sb + STAGE_BYTES, sPrv = sb + 2 * STAGE_BYTES;

    load_stage(sCur);
    load_stage(sNxt);

    // Double-buffered fragments: buffer (kk & 1) is consumed, other prefetched.
    uint32_t fa[2][4][4], fb[2][4][4];

    for (int it = 0; it < NCHUNK; it++) {
        CP_WAIT(0);              // everything issued through it+1 is complete
        __syncthreads();

        if (it == 0) {
            // prolog: kk=0 fragments into buffer 0
#pragma unroll
            for (int fm = 0; fm < 4; fm++)
                ldsm4(fa[0][fm][0], fa[0][fm][1], fa[0][fm][2], fa[0][fm][3],
                      sCur + offA[fm]);
#pragma unroll
            for (int f = 0; f < 4; f++)
                ldsm4(fb[0][f][0], fb[0][f][1], fb[0][f][2], fb[0][f][3],
                      sCur + TILE16K + offB[f]);
        }

        if (it + 2 < NCHUNK) load_stage(sPrv);

#pragma unroll
        for (int kk = 0; kk < 4; kk++) {
            const int cb = kk & 1;
            const int nb = cb ^ 1;
            // Prefetch next fragment set behind this kk's MMA stream
            if (kk < 3) {
                const uint32_t kx = (uint32_t)(kk + 1) << 5;
#pragma unroll
                for (int fm = 0; fm < 4; fm++)
                    ldsm4(fa[nb][fm][0], fa[nb][fm][1], fa[nb][fm][2], fa[nb][fm][3],
                          sCur + (offA[fm] ^ kx));
#pragma unroll
                for (int f = 0; f < 4; f++)
                    ldsm4(fb[nb][f][0], fb[nb][f][1], fb[nb][f][2], fb[nb][f][3],
                          sCur + TILE16K + (offB[f] ^ kx));
            } else if (it + 1 < NCHUNK) {
                // next stage's kk=0 (sNxt is complete; its slot is rewritten
                // only after two more barriers)
#pragma unroll
                for (int fm = 0; fm < 4; fm++)
                    ldsm4(fa[nb][fm][0], fa[nb][fm][1], fa[nb][fm][2], fa[nb][fm][3],
                          sNxt + offA[fm]);
#pragma unroll
                for (int f = 0; f < 4; f++)
                    ldsm4(fb[nb][f][0], fb[nb][f][1], fb[nb][f][2], fb[nb][f][3],
                          sNxt + TILE16K + offB[f]);
            }

#pragma unroll
            for (int fm = 0; fm < 4; fm++)
#pragma unroll
                for (int fn = 0; fn < 8; fn++) {
                    const int fbx = fn >> 1, hh = fn & 1;
                    mma16816(acc[fm][fn][0], acc[fm][fn][1], acc[fm][fn][2], acc[fm][fn][3],
                             fa[cb][fm][0], fa[cb][fm][1], fa[cb][fm][2], fa[cb][fm][3],
                             fb[cb][fbx][hh], fb[cb][fbx][hh + 2]);
                }
        }

        const uint32_t t = sPrv;
        sPrv = sCur; sCur = sNxt; sNxt = t;
    }

    const int lr = lid >> 2;
    const int lc = (lid & 3) * 2;

    if (HALF_OUT) {
        __syncthreads();
        __half* sh = (__half*)smem;
#pragma unroll
        for (int fm = 0; fm < 4; fm++) {
#pragma unroll
            for (int fn = 0; fn < 8; fn++) {
                const int col = warp_n + fn * 8 + lc;
                const float b0 = bias[bn + col], b1 = bias[bn + col + 1];
                const int row0 = warp_m + fm * 16 + lr;
                __half2 h0 = __floats2half2_rn(acc[fm][fn][0] + b0, acc[fm][fn][1] + b1);
                __half2 h1 = __floats2half2_rn(acc[fm][fn][2] + b0, acc[fm][fn][3] + b1);
                *(__half2*)(sh + row0 * SROW + col)       = h0;
                *(__half2*)(sh + (row0 + 8) * SROW + col) = h1;
            }
        }
        __syncthreads();
        __half* C = (__half*)Cv;
#pragma unroll
        for (int i = 0; i < 16; i++) {
            const int idx = tid + 128 * i;
            const int row = idx >> 4;
            const int c8  = (idx & 15) * 8;
            const uint4 vv = *(const uint4*)(sh + row * SROW + c8);
            *(uint4*)(C + (size_t)(bm + row) * N + bn + c8) = vv;
        }
    } else {
        float* C = (float*)Cv;
#pragma unroll
        for (int fm = 0; fm < 4; fm++) {
#pragma unroll
            for (int fn = 0; fn < 8; fn++) {
                const int col = bn + warp_n + fn * 8 + lc;
                const float b0 = bias[col], b1 = bias[col + 1];
                const int row0 = bm + warp_m + fm * 16 + lr;
                float2 v0 = { acc[fm][fn][0] + b0, acc[fm][fn][1] + b1 };
                float2 v1 = { acc[fm][fn][2] + b0, acc[fm][fn][3] + b1 };
                *(float2*)(C + (size_t)row0 * N + col)       = v0;
                *(float2*)(C + (size_t)(row0 + 8) * N + col) = v1;
            }
        }
    }
}

// ---------------------------------------------------------------------------
// MMA attention (R16, frozen): CTA = (s, head-group of 4), warp = head.
// ---------------------------------------------------------------------------
#define RS    72
#define HSEG  (16 * RS)
#define ATT_SMEM ((12 * HSEG + 4 * HSEG) * 2)

__global__ void __launch_bounds__(128, 6) attn_kernel(
    const __half* __restrict__ qkv, __half* __restrict__ oh)
{
    const int s = blockIdx.x;
    const int g = blockIdx.y;
    extern __shared__ char smraw[];
    __half* smh = (__half*)smraw;
    const uint32_t sb = smem_u32(smraw);
    const int tid = threadIdx.x;

#pragma unroll
    for (int i = 0; i < 12; i++) {
        const int idx = tid + 128 * i;
        const int ch  = idx & 7;
        const int b   = (idx >> 3) & 15;
        const int hd  = (idx >> 7) & 3;
        const int rg  = idx >> 9;
        const __half* src = qkv + ((size_t)(b * SDIM + s)) * 1536
                          + rg * 512 + (g * 4 + hd) * 64 + ch * 8;
        const uint32_t dsth = (uint32_t)((rg * 4 + hd) * HSEG + b * RS + ch * 8);
        cpa16(sb + dsth * 2, src);
    }
    CP_COMMIT();
    CP_WAIT(0);
    __syncthreads();

    const int w   = tid >> 5;
    const int lid = tid & 31;
    const int lr  = lid >> 2;
    const int lc  = lid & 3;

    const uint32_t qb = sb + (uint32_t)((0 + w) * HSEG) * 2;
    const uint32_t kb = sb + (uint32_t)((4 + w) * HSEG) * 2;
    const uint32_t vb = sb + (uint32_t)((8 + w) * HSEG) * 2;
    __half* os = smh + (12 + w) * HSEG;

    const uint32_t lOff = (uint32_t)((lid & 15) * (RS * 2) + (lid >> 4) * 16);

    float s0[4] = {0.f, 0.f, 0.f, 0.f};
    float s1[4] = {0.f, 0.f, 0.f, 0.f};
#pragma unroll
    for (int t = 0; t < 4; t++) {
        uint32_t a0, a1, a2, a3, k0, k1, k2, k3;
        ldsm4(a0, a1, a2, a3, qb + lOff + t * 32);
        ldsm4(k0, k1, k2, k3, kb + lOff + t * 32);
        mma16816(s0[0], s0[1], s0[2], s0[3], a0, a1, a2, a3, k0, k2);
        mma16816(s1[0], s1[1], s1[2], s1[3], a0, a1, a2, a3, k1, k3);
    }

    const float scl = 0.125f;
#pragma unroll
    for (int j = 0; j < 4; j++) { s0[j] *= scl; s1[j] *= scl; }

    float m0 = fmaxf(fmaxf(s0[0], s0[1]), fmaxf(s1[0], s1[1]));
    m0 = fmaxf(m0, __shfl_xor_sync(0xffffffffu, m0, 1));
    m0 = fmaxf(m0, __shfl_xor_sync(0xffffffffu, m0, 2));
    float m1 = fmaxf(fmaxf(s0[2], s0[3]), fmaxf(s1[2], s1[3]));
    m1 = fmaxf(m1, __shfl_xor_sync(0xffffffffu, m1, 1));
    m1 = fmaxf(m1, __shfl_xor_sync(0xffffffffu, m1, 2));

    float p00 = expf(s0[0] - m0), p01 = expf(s0[1] - m0);
    float p10 = expf(s1[0] - m0), p11 = expf(s1[1] - m0);
    float q00 = expf(s0[2] - m1), q01 = expf(s0[3] - m1);
    float q10 = expf(s1[2] - m1), q11 = expf(s1[3] - m1);

    float sum0 = p00 + p01 + p10 + p11;
    sum0 += __shfl_xor_sync(0xffffffffu, sum0, 1);
    sum0 += __shfl_xor_sync(0xffffffffu, sum0, 2);
    float sum1 = q00 + q01 + q10 + q11;
    sum1 += __shfl_xor_sync(0xffffffffu, sum1, 1);
    sum1 += __shfl_xor_sync(0xffffffffu, sum1, 2);
    const float i0 = 1.0f / sum0;
    const float i1 = 1.0f / sum1;

    __half2 ha0 = __floats2half2_rn(p00 * i0, p01 * i0);
    __half2 ha1 = __floats2half2_rn(q00 * i1, q01 * i1);
    __half2 ha2 = __floats2half2_rn(p10 * i0, p11 * i0);
    __half2 ha3 = __floats2half2_rn(q10 * i1, q11 * i1);
    const uint32_t pa0 = *(uint32_t*)&ha0;
    const uint32_t pa1 = *(uint32_t*)&ha1;
    const uint32_t pa2 = *(uint32_t*)&ha2;
    const uint32_t pa3 = *(uint32_t*)&ha3;

    float o[8][4];
#pragma unroll
    for (int i = 0; i < 8; i++)
#pragma unroll
        for (int r = 0; r < 4; r++) o[i][r] = 0.0f;

#pragma unroll
    for (int t = 0; t < 4; t++) {
        uint32_t v0, v1, v2, v3;
        ldsm4t(v0, v1, v2, v3, vb + lOff + t * 32);
        mma16816(o[2 * t][0], o[2 * t][1], o[2 * t][2], o[2 * t][3],
                 pa0, pa1, pa2, pa3, v0, v1);
        mma16816(o[2 * t + 1][0], o[2 * t + 1][1], o[2 * t + 1][2], o[2 * t + 1][3],
                 pa0, pa1, pa2, pa3, v2, v3);
    }

#pragma unroll
    for (int nt = 0; nt < 8; nt++) {
        __half2 h0 = __floats2half2_rn(o[nt][0], o[nt][1]);
        __half2 h1 = __floats2half2_rn(o[nt][2], o[nt][3]);
        *(__half2*)(os + lr * RS + nt * 8 + 2 * lc)       = h0;
        *(__half2*)(os + (lr + 8) * RS + nt * 8 + 2 * lc) = h1;
    }
    __syncthreads();

#pragma unroll
    for (int i = 0; i < 4; i++) {
        const int idx = tid + 128 * i;
        const int row = idx >> 5;
        const int c8  = (idx & 31) * 8;
        const int hd2 = c8 >> 6;
        const int within = c8 & 63;
        const uint4 vv = *(const uint4*)(smh + (12 + hd2) * HSEG + row * RS + within);
        *(uint4*)(oh + ((size_t)(row * SDIM + s)) * EDIM + g * 256 + c8) = vv;
    }
}

// ---------------------------------------------------------------------------
extern "C" void kernel_launch(void* const* d_in, const int* in_sizes, int n_in,
                              void* d_out, int out_size)
{
    const float* x     = (const float*)d_in[0];
    const float* W_in  = (const float*)d_in[1];
    const float* b_in  = (const float*)d_in[2];
    const float* W_out = (const float*)d_in[3];
    const float* b_out = (const float*)d_in[4];
    float* out = (float*)d_out;

    __half *qkv, *xh, *oh, *winh, *wouth;
    cudaGetSymbolAddress((void**)&qkv, g_qkv);
    cudaGetSymbolAddress((void**)&xh, g_xh);
    cudaGetSymbolAddress((void**)&oh, g_oh);
    cudaGetSymbolAddress((void**)&winh, g_winh);
    cudaGetSymbolAddress((void**)&wouth, g_wouth);

    cudaFuncSetAttribute(gemm_hmma<true>,  cudaFuncAttributeMaxDynamicSharedMemorySize, GEMM_SMEM);
    cudaFuncSetAttribute(gemm_hmma<false>, cudaFuncAttributeMaxDynamicSharedMemorySize, GEMM_SMEM);
    cudaFuncSetAttribute(attn_kernel, cudaFuncAttributeMaxDynamicSharedMemorySize, ATT_SMEM);

    // fp32 -> fp16 conversions (single launch)
    conv_all<<<NB_X + NB_WI + NB_WO, 256>>>(
        (const float4*)x, (uint2*)xh,
        (const float4*)W_in, (uint2*)winh,
        (const float4*)W_out, (uint2*)wouth);

    // 1) QKV projection -> fp16 qkv
    dim3 g1(3 * EDIM / 128, TOK / 128);
    gemm_hmma<true><<<g1, 128, GEMM_SMEM>>>(xh, winh, b_in, qkv, 3 * EDIM);

    // 2) MMA attention
    dim3 g2(SDIM, HDIM / 4);
    attn_kernel<<<g2, 128, ATT_SMEM>>>(qkv, oh);

    // 3) Output projection -> fp32 out
    dim3 g3(EDIM / 128, TOK / 128);
    gemm_hmma<false><<<g3, 128, GEMM_SMEM>>>(oh, wouth, b_out, out, EDIM);
}